// round 1
// baseline (speedup 1.0000x reference)
#include <cuda_runtime.h>
#include <cuda_bf16.h>
#include <cstdint>

// Problem dims (fixed)
#define BATCH 2
#define SEQ   2048
#define DIM   4096
#define NH    32
#define NKV   8
#define HD    128
#define NREP  4
#define MTOT  (BATCH*SEQ)          // 4096

// ---------------- scratch (static device globals; no allocation) ----------
__device__ float g_xq[(size_t)MTOT * NH * HD];     // 4096 x 4096
__device__ float g_xk[(size_t)MTOT * NKV * HD];    // 4096 x 1024
__device__ float g_xv[(size_t)MTOT * NKV * HD];    // 4096 x 1024
__device__ float g_attn[(size_t)MTOT * NH * HD];   // 4096 x 4096

// ---------------- SGEMM: C[M,N] = A[M,K] @ B[K,N], fp32, all dims %128==0 --
#define GBM 128
#define GBN 128
#define GBK 8

__global__ __launch_bounds__(256)
void sgemm_kernel(const float* __restrict__ A, const float* __restrict__ B,
                  float* __restrict__ C, int M, int N, int K)
{
    __shared__ float As[GBK][GBM + 4];
    __shared__ float Bs[GBK][GBN + 4];

    const int tid = threadIdx.x;
    const int tx = tid & 15;          // 0..15  (N dir)
    const int ty = tid >> 4;          // 0..15  (M dir)
    const int bm = blockIdx.y * GBM;
    const int bn = blockIdx.x * GBN;

    const float* Ab = A + (size_t)bm * K;
    const float* Bb = B + bn;

    const int a_row = tid >> 1;             // 0..127
    const int a_col = (tid & 1) << 2;       // 0 or 4
    const int b_row = tid >> 5;             // 0..7
    const int b_col = (tid & 31) << 2;      // 0..124

    float acc[8][8];
#pragma unroll
    for (int i = 0; i < 8; i++)
#pragma unroll
        for (int j = 0; j < 8; j++) acc[i][j] = 0.f;

    for (int k0 = 0; k0 < K; k0 += GBK) {
        float4 av = *(const float4*)(Ab + (size_t)a_row * K + k0 + a_col);
        float4 bv = *(const float4*)(Bb + (size_t)(k0 + b_row) * N + b_col);
        __syncthreads();
        As[a_col + 0][a_row] = av.x;
        As[a_col + 1][a_row] = av.y;
        As[a_col + 2][a_row] = av.z;
        As[a_col + 3][a_row] = av.w;
        *(float4*)&Bs[b_row][b_col] = bv;
        __syncthreads();

#pragma unroll
        for (int kk = 0; kk < GBK; kk++) {
            float a_reg[8], b_reg[8];
            *(float4*)&a_reg[0] = *(const float4*)&As[kk][ty * 8];
            *(float4*)&a_reg[4] = *(const float4*)&As[kk][ty * 8 + 4];
            *(float4*)&b_reg[0] = *(const float4*)&Bs[kk][tx * 8];
            *(float4*)&b_reg[4] = *(const float4*)&Bs[kk][tx * 8 + 4];
#pragma unroll
            for (int i = 0; i < 8; i++)
#pragma unroll
                for (int j = 0; j < 8; j++)
                    acc[i][j] += a_reg[i] * b_reg[j];
        }
    }

    float* Cb = C + (size_t)bm * N + bn;
#pragma unroll
    for (int i = 0; i < 8; i++) {
        float4 v0, v1;
        v0.x = acc[i][0]; v0.y = acc[i][1]; v0.z = acc[i][2]; v0.w = acc[i][3];
        v1.x = acc[i][4]; v1.y = acc[i][5]; v1.z = acc[i][6]; v1.w = acc[i][7];
        *(float4*)(Cb + (size_t)(ty * 8 + i) * N + tx * 8)     = v0;
        *(float4*)(Cb + (size_t)(ty * 8 + i) * N + tx * 8 + 4) = v1;
    }
}

// ---------------- RoPE (in place). Pair index is innermost in memory. ------
__global__ __launch_bounds__(256)
void rope_kernel(float2* __restrict__ x, const float* __restrict__ cs,
                 const float* __restrict__ sn, int heads)
{
    const int idx = blockIdx.x * blockDim.x + threadIdx.x;
    const int pair = idx & 63;                 // HD/2 = 64
    const int row  = idx >> 6;                 // (b*SEQ + s)*heads + h
    const int s    = (row / heads) & (SEQ - 1);
    const float c  = cs[s * 64 + pair];
    const float si = sn[s * 64 + pair];
    float2 v = x[idx];
    float2 o;
    o.x = v.x * c - v.y * si;
    o.y = v.x * si + v.y * c;
    x[idx] = o;
}

// ---------------- Flash attention fp32 (non-causal, full S) ---------------
// grid: (SEQ/64, NH, BATCH), block: 128 threads
// smem: Qs[64][132] + Kts[128][66] + Vs[64][132] + Ps[64][65]
#define ATT_QS_F   (64 * 132)
#define ATT_KT_F   (128 * 66)
#define ATT_VS_F   (64 * 132)
#define ATT_PS_F   (64 * 65)
#define ATT_SMEM   ((ATT_QS_F + ATT_KT_F + ATT_VS_F + ATT_PS_F) * 4)

__global__ __launch_bounds__(128)
void attention_kernel(const float* __restrict__ q, const float* __restrict__ k,
                      const float* __restrict__ v, float* __restrict__ o)
{
    extern __shared__ float sm[];
    float (*Qs)[132] = (float(*)[132])sm;
    float (*Kts)[66] = (float(*)[66])(sm + ATT_QS_F);
    float (*Vs)[132] = (float(*)[132])(sm + ATT_QS_F + ATT_KT_F);
    float (*Ps)[65]  = (float(*)[65]) (sm + ATT_QS_F + ATT_KT_F + ATT_VS_F);

    const int tid = threadIdx.x;
    const int tx = tid & 7;      // key-col group (0..7)
    const int ty = tid >> 3;     // query-row group (0..15)
    const int b  = blockIdx.z;
    const int h  = blockIdx.y;
    const int kvh = h >> 2;      // NREP = 4
    const int q0 = blockIdx.x * 64;

    const float inv_sqrt = 0.08838834764831845f;   // 1/sqrt(128)

    // load Q tile (scaled)
    const float* qbase = q + ((size_t)(b * SEQ + q0) * NH + h) * HD;
#pragma unroll
    for (int i = tid; i < 64 * 32; i += 128) {
        int r = i >> 5, c4 = (i & 31) << 2;
        float4 qv = *(const float4*)(qbase + (size_t)r * (NH * HD) + c4);
        Qs[r][c4 + 0] = qv.x * inv_sqrt;
        Qs[r][c4 + 1] = qv.y * inv_sqrt;
        Qs[r][c4 + 2] = qv.z * inv_sqrt;
        Qs[r][c4 + 3] = qv.w * inv_sqrt;
    }

    float m_run[4], l_run[4], o_acc[4][16];
#pragma unroll
    for (int i = 0; i < 4; i++) {
        m_run[i] = -1e30f;
        l_run[i] = 0.f;
#pragma unroll
        for (int j = 0; j < 16; j++) o_acc[i][j] = 0.f;
    }

    const float* kbase = k + ((size_t)(b * SEQ) * NKV + kvh) * HD;
    const float* vbase = v + ((size_t)(b * SEQ) * NKV + kvh) * HD;

    for (int t0 = 0; t0 < SEQ; t0 += 64) {
        __syncthreads();   // protect Kts/Vs/Ps from previous iteration readers
        const float* kb = kbase + (size_t)t0 * (NKV * HD);
        const float* vb = vbase + (size_t)t0 * (NKV * HD);
#pragma unroll
        for (int i = tid; i < 64 * 32; i += 128) {
            int r = i >> 5, c4 = (i & 31) << 2;
            float4 kv = *(const float4*)(kb + (size_t)r * (NKV * HD) + c4);
            Kts[c4 + 0][r] = kv.x;
            Kts[c4 + 1][r] = kv.y;
            Kts[c4 + 2][r] = kv.z;
            Kts[c4 + 3][r] = kv.w;
            float4 vv = *(const float4*)(vb + (size_t)r * (NKV * HD) + c4);
            *(float4*)&Vs[r][c4] = vv;
        }
        __syncthreads();

        // S = Q @ K^T  (4 rows x 8 cols per thread)
        float s[4][8];
#pragma unroll
        for (int i = 0; i < 4; i++)
#pragma unroll
            for (int j = 0; j < 8; j++) s[i][j] = 0.f;

#pragma unroll 8
        for (int kk = 0; kk < HD; kk++) {
            float qr[4], kc[8];
#pragma unroll
            for (int i = 0; i < 4; i++) qr[i] = Qs[ty * 4 + i][kk];
#pragma unroll
            for (int j = 0; j < 8; j++) kc[j] = Kts[kk][tx * 8 + j];
#pragma unroll
            for (int i = 0; i < 4; i++)
#pragma unroll
                for (int j = 0; j < 8; j++)
                    s[i][j] += qr[i] * kc[j];
        }

        // online softmax (rows shared by the 8 lanes with equal ty, within warp)
#pragma unroll
        for (int i = 0; i < 4; i++) {
            float mx = s[i][0];
#pragma unroll
            for (int j = 1; j < 8; j++) mx = fmaxf(mx, s[i][j]);
            mx = fmaxf(mx, __shfl_xor_sync(0xffffffffu, mx, 1));
            mx = fmaxf(mx, __shfl_xor_sync(0xffffffffu, mx, 2));
            mx = fmaxf(mx, __shfl_xor_sync(0xffffffffu, mx, 4));
            float m_new = fmaxf(m_run[i], mx);
            float scale = __expf(m_run[i] - m_new);
            float rs = 0.f;
#pragma unroll
            for (int j = 0; j < 8; j++) {
                float p = __expf(s[i][j] - m_new);
                s[i][j] = p;
                rs += p;
            }
            rs += __shfl_xor_sync(0xffffffffu, rs, 1);
            rs += __shfl_xor_sync(0xffffffffu, rs, 2);
            rs += __shfl_xor_sync(0xffffffffu, rs, 4);
            l_run[i] = l_run[i] * scale + rs;
            m_run[i] = m_new;
#pragma unroll
            for (int j = 0; j < 16; j++) o_acc[i][j] *= scale;
        }

        // stage P through smem
#pragma unroll
        for (int i = 0; i < 4; i++)
#pragma unroll
            for (int j = 0; j < 8; j++)
                Ps[ty * 4 + i][tx * 8 + j] = s[i][j];
        __syncthreads();

        // O += P @ V  (4 rows x 16 cols per thread)
#pragma unroll 8
        for (int c = 0; c < 64; c++) {
            float p[4];
#pragma unroll
            for (int i = 0; i < 4; i++) p[i] = Ps[ty * 4 + i][c];
#pragma unroll
            for (int jj = 0; jj < 4; jj++) {
                float4 vv = *(const float4*)&Vs[c][tx * 16 + jj * 4];
#pragma unroll
                for (int i = 0; i < 4; i++) {
                    o_acc[i][jj * 4 + 0] += p[i] * vv.x;
                    o_acc[i][jj * 4 + 1] += p[i] * vv.y;
                    o_acc[i][jj * 4 + 2] += p[i] * vv.z;
                    o_acc[i][jj * 4 + 3] += p[i] * vv.w;
                }
            }
        }
    }

    // normalize + write out (layout (b, s, h, d) = (b, s, NH*HD) row-major)
    float* obase = o + ((size_t)(b * SEQ + q0) * NH + h) * HD;
#pragma unroll
    for (int i = 0; i < 4; i++) {
        int r = ty * 4 + i;
        float inv_l = 1.f / l_run[i];
#pragma unroll
        for (int jj = 0; jj < 4; jj++) {
            float4 ov;
            ov.x = o_acc[i][jj * 4 + 0] * inv_l;
            ov.y = o_acc[i][jj * 4 + 1] * inv_l;
            ov.z = o_acc[i][jj * 4 + 2] * inv_l;
            ov.w = o_acc[i][jj * 4 + 3] * inv_l;
            *(float4*)(obase + (size_t)r * (NH * HD) + tx * 16 + jj * 4) = ov;
        }
    }
}

// ---------------- launch -------------------------------------------------
extern "C" void kernel_launch(void* const* d_in, const int* in_sizes, int n_in,
                              void* d_out, int out_size)
{
    (void)in_sizes; (void)n_in; (void)out_size;
    const float* x  = (const float*)d_in[0];
    const float* wq = (const float*)d_in[1];
    const float* wk = (const float*)d_in[2];
    const float* wv = (const float*)d_in[3];
    const float* wo = (const float*)d_in[4];
    const float* fc = (const float*)d_in[5];
    const float* fs = (const float*)d_in[6];
    // d_in[7] cache_k, d_in[8] cache_v, d_in[9] start_pos: zeros / 0 -> unused
    float* out = (float*)d_out;

    float *xq, *xk, *xv, *attn;
    cudaGetSymbolAddress((void**)&xq,   g_xq);
    cudaGetSymbolAddress((void**)&xk,   g_xk);
    cudaGetSymbolAddress((void**)&xv,   g_xv);
    cudaGetSymbolAddress((void**)&attn, g_attn);

    // QKV projections
    sgemm_kernel<<<dim3(DIM / GBN, MTOT / GBM), 256>>>(x, wq, xq, MTOT, DIM, DIM);
    sgemm_kernel<<<dim3((NKV * HD) / GBN, MTOT / GBM), 256>>>(x, wk, xk, MTOT, NKV * HD, DIM);
    sgemm_kernel<<<dim3((NKV * HD) / GBN, MTOT / GBM), 256>>>(x, wv, xv, MTOT, NKV * HD, DIM);

    // RoPE on q and k
    rope_kernel<<<(MTOT * NH * (HD / 2)) / 256, 256>>>((float2*)xq, fc, fs, NH);
    rope_kernel<<<(MTOT * NKV * (HD / 2)) / 256, 256>>>((float2*)xk, fc, fs, NKV);

    // attention
    cudaFuncSetAttribute(attention_kernel,
                         cudaFuncAttributeMaxDynamicSharedMemorySize, ATT_SMEM);
    attention_kernel<<<dim3(SEQ / 64, NH, BATCH), 128, ATT_SMEM>>>(xq, xk, xv, attn);

    // output projection
    sgemm_kernel<<<dim3(DIM / GBN, MTOT / GBM), 256>>>(attn, wo, out, MTOT, DIM, DIM);
}

// round 2
// speedup vs baseline: 1.5511x; 1.5511x over previous
#include <cuda_runtime.h>
#include <cuda_bf16.h>
#include <cstdint>

// Problem dims (fixed)
#define BATCH 2
#define SEQ   2048
#define DIM   4096
#define NH    32
#define NKV   8
#define HD    128
#define NREP  4
#define MTOT  (BATCH*SEQ)          // 4096

// ---------------- scratch (static device globals; no allocation) ----------
__device__ float g_xq[(size_t)MTOT * NH * HD];     // 4096 x 4096
__device__ float g_xk[(size_t)MTOT * NKV * HD];    // 4096 x 1024
__device__ float g_xv[(size_t)MTOT * NKV * HD];    // 4096 x 1024
__device__ float g_attn[(size_t)MTOT * NH * HD];   // 4096 x 4096

// ================= tf32 tensor-core GEMM: C = A @ B ======================
// A[M,K] row-major, B[K,N] row-major, C[M,N] row-major, fp32 in/out.
// Block tile 128x128x32, 256 threads, 8 warps in 4(M) x 2(N),
// warp tile 32x64 -> 2 m-frags x 8 n-frags of m16n8k8 tf32 mma.
#define TBM 128
#define TBN 128
#define TBK 32
#define TSMEM (2 * (TBK * (TBM + 4) + TBK * (TBN + 4)) * 4)

__device__ __forceinline__ unsigned f2tf(float f) {
    unsigned u;
    asm("cvt.rna.tf32.f32 %0, %1;" : "=r"(u) : "f"(f));
    return u;
}

__global__ __launch_bounds__(256)
void tf32_gemm(const float* __restrict__ A, const float* __restrict__ B,
               float* __restrict__ C, int M, int N, int K)
{
    extern __shared__ unsigned smem[];
    // As[buf][k][m], Bs[buf][k][n]
    unsigned (*As)[TBK][TBM + 4] = (unsigned(*)[TBK][TBM + 4])smem;
    unsigned (*Bs)[TBK][TBN + 4] =
        (unsigned(*)[TBK][TBN + 4])(smem + 2 * TBK * (TBM + 4));

    const int tid  = threadIdx.x;
    const int wid  = tid >> 5;
    const int lane = tid & 31;
    const int warpM = wid >> 1;          // 0..3
    const int warpN = wid & 1;           // 0..1
    const int g = lane >> 2;             // group id 0..7
    const int c = lane & 3;              // thread-in-group

    const int bm = blockIdx.y * TBM;
    const int bn = blockIdx.x * TBN;

    float acc[2][8][4];
#pragma unroll
    for (int i = 0; i < 2; i++)
#pragma unroll
        for (int j = 0; j < 8; j++)
#pragma unroll
            for (int r = 0; r < 4; r++) acc[i][j][r] = 0.f;

    // global load staging (4 float4 each for A and B per thread)
    float4 ar[4], br[4];

    // A tile: 128 rows x 32 k -> 1024 float4; thread v: linear = v*256+tid
    //   arow = linear>>3, acol4 = (linear&7)*4
    // B tile: 32 k x 128 n  -> 1024 float4; brow = linear>>5, bcol4=(linear&31)*4
    const int nt = K / TBK;

    auto load_g = [&](int t) {
#pragma unroll
        for (int v = 0; v < 4; v++) {
            int lin = v * 256 + tid;
            int arow = lin >> 3, acol = (lin & 7) << 2;
            ar[v] = *(const float4*)(A + (size_t)(bm + arow) * K + t * TBK + acol);
            int brow = lin >> 5, bcol = (lin & 31) << 2;
            br[v] = *(const float4*)(B + (size_t)(t * TBK + brow) * N + bn + bcol);
        }
    };
    auto store_s = [&](int buf) {
#pragma unroll
        for (int v = 0; v < 4; v++) {
            int lin = v * 256 + tid;
            int arow = lin >> 3, acol = (lin & 7) << 2;
            As[buf][acol + 0][arow] = f2tf(ar[v].x);
            As[buf][acol + 1][arow] = f2tf(ar[v].y);
            As[buf][acol + 2][arow] = f2tf(ar[v].z);
            As[buf][acol + 3][arow] = f2tf(ar[v].w);
            int brow = lin >> 5, bcol = (lin & 31) << 2;
            uint4 bv;
            bv.x = f2tf(br[v].x); bv.y = f2tf(br[v].y);
            bv.z = f2tf(br[v].z); bv.w = f2tf(br[v].w);
            *(uint4*)&Bs[buf][brow][bcol] = bv;
        }
    };

    load_g(0);
    store_s(0);
    __syncthreads();

    for (int t = 0; t < nt; t++) {
        int cur = t & 1;
        if (t + 1 < nt) load_g(t + 1);

#pragma unroll
        for (int ks = 0; ks < 4; ks++) {
            const int k0 = ks * 8;
            unsigned a[2][4], b[8][2];
#pragma unroll
            for (int i = 0; i < 2; i++) {
                int m = warpM * 32 + i * 16 + g;
                a[i][0] = As[cur][k0 + c][m];
                a[i][1] = As[cur][k0 + c][m + 8];
                a[i][2] = As[cur][k0 + c + 4][m];
                a[i][3] = As[cur][k0 + c + 4][m + 8];
            }
#pragma unroll
            for (int j = 0; j < 8; j++) {
                int n = warpN * 64 + j * 8 + g;
                b[j][0] = Bs[cur][k0 + c][n];
                b[j][1] = Bs[cur][k0 + c + 4][n];
            }
#pragma unroll
            for (int i = 0; i < 2; i++)
#pragma unroll
                for (int j = 0; j < 8; j++) {
                    asm volatile(
                        "mma.sync.aligned.m16n8k8.row.col.f32.tf32.tf32.f32 "
                        "{%0,%1,%2,%3},{%4,%5,%6,%7},{%8,%9},{%0,%1,%2,%3};"
                        : "+f"(acc[i][j][0]), "+f"(acc[i][j][1]),
                          "+f"(acc[i][j][2]), "+f"(acc[i][j][3])
                        : "r"(a[i][0]), "r"(a[i][1]), "r"(a[i][2]), "r"(a[i][3]),
                          "r"(b[j][0]), "r"(b[j][1]));
                }
        }

        if (t + 1 < nt) store_s(cur ^ 1);
        __syncthreads();
    }

    // epilogue: float2 stores
#pragma unroll
    for (int i = 0; i < 2; i++) {
        int row = bm + warpM * 32 + i * 16 + g;
#pragma unroll
        for (int j = 0; j < 8; j++) {
            int col = bn + warpN * 64 + j * 8 + 2 * c;
            float2 v0, v1;
            v0.x = acc[i][j][0]; v0.y = acc[i][j][1];
            v1.x = acc[i][j][2]; v1.y = acc[i][j][3];
            *(float2*)(C + (size_t)row * N + col)       = v0;
            *(float2*)(C + (size_t)(row + 8) * N + col) = v1;
        }
    }
}

// ---------------- RoPE (in place). Pair index is innermost in memory. ------
__global__ __launch_bounds__(256)
void rope_kernel(float2* __restrict__ x, const float* __restrict__ cs,
                 const float* __restrict__ sn, int heads)
{
    const int idx = blockIdx.x * blockDim.x + threadIdx.x;
    const int pair = idx & 63;                 // HD/2 = 64
    const int row  = idx >> 6;                 // (b*SEQ + s)*heads + h
    const int s    = (row / heads) & (SEQ - 1);
    const float c  = cs[s * 64 + pair];
    const float si = sn[s * 64 + pair];
    float2 v = x[idx];
    float2 o;
    o.x = v.x * c - v.y * si;
    o.y = v.x * si + v.y * c;
    x[idx] = o;
}

// ---------------- Flash attention fp32 (non-causal, full S) ---------------
#define ATT_QS_F   (64 * 132)
#define ATT_KT_F   (128 * 66)
#define ATT_VS_F   (64 * 132)
#define ATT_PS_F   (64 * 65)
#define ATT_SMEM   ((ATT_QS_F + ATT_KT_F + ATT_VS_F + ATT_PS_F) * 4)

__global__ __launch_bounds__(128)
void attention_kernel(const float* __restrict__ q, const float* __restrict__ k,
                      const float* __restrict__ v, float* __restrict__ o)
{
    extern __shared__ float sm[];
    float (*Qs)[132] = (float(*)[132])sm;
    float (*Kts)[66] = (float(*)[66])(sm + ATT_QS_F);
    float (*Vs)[132] = (float(*)[132])(sm + ATT_QS_F + ATT_KT_F);
    float (*Ps)[65]  = (float(*)[65]) (sm + ATT_QS_F + ATT_KT_F + ATT_VS_F);

    const int tid = threadIdx.x;
    const int tx = tid & 7;      // key-col group (0..7)
    const int ty = tid >> 3;     // query-row group (0..15)
    const int b  = blockIdx.z;
    const int h  = blockIdx.y;
    const int kvh = h >> 2;      // NREP = 4
    const int q0 = blockIdx.x * 64;

    const float inv_sqrt = 0.08838834764831845f;   // 1/sqrt(128)

    const float* qbase = q + ((size_t)(b * SEQ + q0) * NH + h) * HD;
#pragma unroll
    for (int i = tid; i < 64 * 32; i += 128) {
        int r = i >> 5, c4 = (i & 31) << 2;
        float4 qv = *(const float4*)(qbase + (size_t)r * (NH * HD) + c4);
        Qs[r][c4 + 0] = qv.x * inv_sqrt;
        Qs[r][c4 + 1] = qv.y * inv_sqrt;
        Qs[r][c4 + 2] = qv.z * inv_sqrt;
        Qs[r][c4 + 3] = qv.w * inv_sqrt;
    }

    float m_run[4], l_run[4], o_acc[4][16];
#pragma unroll
    for (int i = 0; i < 4; i++) {
        m_run[i] = -1e30f;
        l_run[i] = 0.f;
#pragma unroll
        for (int j = 0; j < 16; j++) o_acc[i][j] = 0.f;
    }

    const float* kbase = k + ((size_t)(b * SEQ) * NKV + kvh) * HD;
    const float* vbase = v + ((size_t)(b * SEQ) * NKV + kvh) * HD;

    for (int t0 = 0; t0 < SEQ; t0 += 64) {
        __syncthreads();
        const float* kb = kbase + (size_t)t0 * (NKV * HD);
        const float* vb = vbase + (size_t)t0 * (NKV * HD);
#pragma unroll
        for (int i = tid; i < 64 * 32; i += 128) {
            int r = i >> 5, c4 = (i & 31) << 2;
            float4 kv = *(const float4*)(kb + (size_t)r * (NKV * HD) + c4);
            Kts[c4 + 0][r] = kv.x;
            Kts[c4 + 1][r] = kv.y;
            Kts[c4 + 2][r] = kv.z;
            Kts[c4 + 3][r] = kv.w;
            float4 vv = *(const float4*)(vb + (size_t)r * (NKV * HD) + c4);
            *(float4*)&Vs[r][c4] = vv;
        }
        __syncthreads();

        float s[4][8];
#pragma unroll
        for (int i = 0; i < 4; i++)
#pragma unroll
            for (int j = 0; j < 8; j++) s[i][j] = 0.f;

#pragma unroll 8
        for (int kk = 0; kk < HD; kk++) {
            float qr[4], kc[8];
#pragma unroll
            for (int i = 0; i < 4; i++) qr[i] = Qs[ty * 4 + i][kk];
#pragma unroll
            for (int j = 0; j < 8; j++) kc[j] = Kts[kk][tx * 8 + j];
#pragma unroll
            for (int i = 0; i < 4; i++)
#pragma unroll
                for (int j = 0; j < 8; j++)
                    s[i][j] += qr[i] * kc[j];
        }

#pragma unroll
        for (int i = 0; i < 4; i++) {
            float mx = s[i][0];
#pragma unroll
            for (int j = 1; j < 8; j++) mx = fmaxf(mx, s[i][j]);
            mx = fmaxf(mx, __shfl_xor_sync(0xffffffffu, mx, 1));
            mx = fmaxf(mx, __shfl_xor_sync(0xffffffffu, mx, 2));
            mx = fmaxf(mx, __shfl_xor_sync(0xffffffffu, mx, 4));
            float m_new = fmaxf(m_run[i], mx);
            float scale = __expf(m_run[i] - m_new);
            float rs = 0.f;
#pragma unroll
            for (int j = 0; j < 8; j++) {
                float p = __expf(s[i][j] - m_new);
                s[i][j] = p;
                rs += p;
            }
            rs += __shfl_xor_sync(0xffffffffu, rs, 1);
            rs += __shfl_xor_sync(0xffffffffu, rs, 2);
            rs += __shfl_xor_sync(0xffffffffu, rs, 4);
            l_run[i] = l_run[i] * scale + rs;
            m_run[i] = m_new;
#pragma unroll
            for (int j = 0; j < 16; j++) o_acc[i][j] *= scale;
        }

#pragma unroll
        for (int i = 0; i < 4; i++)
#pragma unroll
            for (int j = 0; j < 8; j++)
                Ps[ty * 4 + i][tx * 8 + j] = s[i][j];
        __syncthreads();

#pragma unroll 8
        for (int cc = 0; cc < 64; cc++) {
            float p[4];
#pragma unroll
            for (int i = 0; i < 4; i++) p[i] = Ps[ty * 4 + i][cc];
#pragma unroll
            for (int jj = 0; jj < 4; jj++) {
                float4 vv = *(const float4*)&Vs[cc][tx * 16 + jj * 4];
#pragma unroll
                for (int i = 0; i < 4; i++) {
                    o_acc[i][jj * 4 + 0] += p[i] * vv.x;
                    o_acc[i][jj * 4 + 1] += p[i] * vv.y;
                    o_acc[i][jj * 4 + 2] += p[i] * vv.z;
                    o_acc[i][jj * 4 + 3] += p[i] * vv.w;
                }
            }
        }
    }

    float* obase = o + ((size_t)(b * SEQ + q0) * NH + h) * HD;
#pragma unroll
    for (int i = 0; i < 4; i++) {
        int r = ty * 4 + i;
        float inv_l = 1.f / l_run[i];
#pragma unroll
        for (int jj = 0; jj < 4; jj++) {
            float4 ov;
            ov.x = o_acc[i][jj * 4 + 0] * inv_l;
            ov.y = o_acc[i][jj * 4 + 1] * inv_l;
            ov.z = o_acc[i][jj * 4 + 2] * inv_l;
            ov.w = o_acc[i][jj * 4 + 3] * inv_l;
            *(float4*)(obase + (size_t)r * (NH * HD) + tx * 16 + jj * 4) = ov;
        }
    }
}

// ---------------- launch -------------------------------------------------
extern "C" void kernel_launch(void* const* d_in, const int* in_sizes, int n_in,
                              void* d_out, int out_size)
{
    (void)in_sizes; (void)n_in; (void)out_size;
    const float* x  = (const float*)d_in[0];
    const float* wq = (const float*)d_in[1];
    const float* wk = (const float*)d_in[2];
    const float* wv = (const float*)d_in[3];
    const float* wo = (const float*)d_in[4];
    const float* fc = (const float*)d_in[5];
    const float* fs = (const float*)d_in[6];
    float* out = (float*)d_out;

    float *xq, *xk, *xv, *attn;
    cudaGetSymbolAddress((void**)&xq,   g_xq);
    cudaGetSymbolAddress((void**)&xk,   g_xk);
    cudaGetSymbolAddress((void**)&xv,   g_xv);
    cudaGetSymbolAddress((void**)&attn, g_attn);

    cudaFuncSetAttribute(tf32_gemm,
                         cudaFuncAttributeMaxDynamicSharedMemorySize, TSMEM);
    cudaFuncSetAttribute(attention_kernel,
                         cudaFuncAttributeMaxDynamicSharedMemorySize, ATT_SMEM);

    // QKV projections (tf32 tensor cores)
    tf32_gemm<<<dim3(DIM / TBN, MTOT / TBM), 256, TSMEM>>>(x, wq, xq, MTOT, DIM, DIM);
    tf32_gemm<<<dim3((NKV * HD) / TBN, MTOT / TBM), 256, TSMEM>>>(x, wk, xk, MTOT, NKV * HD, DIM);
    tf32_gemm<<<dim3((NKV * HD) / TBN, MTOT / TBM), 256, TSMEM>>>(x, wv, xv, MTOT, NKV * HD, DIM);

    // RoPE on q and k
    rope_kernel<<<(MTOT * NH * (HD / 2)) / 256, 256>>>((float2*)xq, fc, fs, NH);
    rope_kernel<<<(MTOT * NKV * (HD / 2)) / 256, 256>>>((float2*)xk, fc, fs, NKV);

    // attention (fp32)
    attention_kernel<<<dim3(SEQ / 64, NH, BATCH), 128, ATT_SMEM>>>(xq, xk, xv, attn);

    // output projection (tf32 tensor cores)
    tf32_gemm<<<dim3(DIM / TBN, MTOT / TBM), 256, TSMEM>>>(attn, wo, out, MTOT, DIM, DIM);
}

// round 4
// speedup vs baseline: 4.2874x; 2.7640x over previous
#include <cuda_runtime.h>
#include <cuda_bf16.h>
#include <cstdint>

// Problem dims (fixed)
#define BATCH 2
#define SEQ   2048
#define DIM   4096
#define NH    32
#define NKV   8
#define HD    128
#define NREP  4
#define MTOT  (BATCH*SEQ)          // 4096
#define KVD   (NKV*HD)             // 1024

// ---------------- scratch (static device globals; no allocation) ----------
__device__ float g_xq[(size_t)MTOT * DIM];
__device__ float g_xk[(size_t)MTOT * KVD];
__device__ float g_xv[(size_t)MTOT * KVD];
__device__ float g_attn[(size_t)MTOT * DIM];
__device__ float g_xr[(size_t)MTOT * DIM];      // tf32-rounded x
__device__ float g_wqr[(size_t)DIM * DIM];
__device__ float g_wkr[(size_t)DIM * KVD];
__device__ float g_wvr[(size_t)DIM * KVD];
__device__ float g_wor[(size_t)DIM * DIM];

__device__ __forceinline__ float f2tf_f(float f) {
    unsigned u;
    asm("cvt.rna.tf32.f32 %0, %1;" : "=r"(u) : "f"(f));
    return __uint_as_float(u);
}

// ---------------- tf32 round pass ----------------------------------------
__global__ __launch_bounds__(256)
void round_kernel(const float4* __restrict__ src, float4* __restrict__ dst)
{
    const int i = blockIdx.x * 256 + threadIdx.x;
    float4 v = src[i];
    v.x = f2tf_f(v.x); v.y = f2tf_f(v.y); v.z = f2tf_f(v.z); v.w = f2tf_f(v.w);
    dst[i] = v;
}

// ================= tf32 tensor-core GEMM v2 ==============================
#define V2_BM 128
#define V2_BN 256
#define V2_BK 32
#define APITCH 36
#define BPITCH 260
#define STG_WORDS (V2_BM * APITCH + V2_BK * BPITCH)   // 12928
#define V2_SMEM (3 * STG_WORDS * 4)                   // 155136 B

__device__ __forceinline__ uint32_t smem_u32(const void* p) {
    uint32_t a;
    asm("{ .reg .u64 t; cvta.to.shared.u64 t, %1; cvt.u32.u64 %0, t; }"
        : "=r"(a) : "l"(p));
    return a;
}
__device__ __forceinline__ void cp16(uint32_t dst, const void* src) {
    asm volatile("cp.async.cg.shared.global [%0], [%1], 16;"
                 :: "r"(dst), "l"(src) : "memory");
}
#define CP_COMMIT() asm volatile("cp.async.commit_group;" ::: "memory")
#define CP_WAIT2()  asm volatile("cp.async.wait_group 2;" ::: "memory")

__device__ __forceinline__ void mma_tf32(float* d, uint32_t a0, uint32_t a1,
                                         uint32_t a2, uint32_t a3,
                                         uint32_t b0, uint32_t b1) {
    asm volatile(
        "mma.sync.aligned.m16n8k8.row.col.f32.tf32.tf32.f32 "
        "{%0,%1,%2,%3},{%4,%5,%6,%7},{%8,%9},{%0,%1,%2,%3};"
        : "+f"(d[0]), "+f"(d[1]), "+f"(d[2]), "+f"(d[3])
        : "r"(a0), "r"(a1), "r"(a2), "r"(a3), "r"(b0), "r"(b1));
}

__global__ __launch_bounds__(256, 1)
void tf32_gemm2(const float* __restrict__ A, const float* __restrict__ B,
                float* __restrict__ C, int M, int N, int K)
{
    extern __shared__ float smem[];
    const int tid  = threadIdx.x;
    const int wid  = tid >> 5;
    const int lane = tid & 31;
    const int warpM = wid >> 2;
    const int warpN = wid & 3;
    const int g = lane >> 2;
    const int c = lane & 3;

    const int bm = blockIdx.y * V2_BM;
    const int bn = blockIdx.x * V2_BN;
    const uint32_t sb = smem_u32(smem);

    float acc[4][8][4];
#pragma unroll
    for (int i = 0; i < 4; i++)
#pragma unroll
        for (int j = 0; j < 8; j++)
#pragma unroll
            for (int r = 0; r < 4; r++) acc[i][j][r] = 0.f;

    const int nt = K / V2_BK;

    auto issue = [&](int t, int buf) {
        const uint32_t base = sb + buf * STG_WORDS * 4;
#pragma unroll
        for (int v = 0; v < 4; v++) {
            int lin = v * 256 + tid;
            int r = lin >> 3, c4 = (lin & 7) << 2;
            cp16(base + (r * APITCH + c4) * 4,
                 A + (size_t)(bm + r) * K + t * V2_BK + c4);
        }
        const uint32_t bbase = base + V2_BM * APITCH * 4;
#pragma unroll
        for (int v = 0; v < 8; v++) {
            int lin = v * 256 + tid;
            int r = lin >> 6, c4 = (lin & 63) << 2;
            cp16(bbase + (r * BPITCH + c4) * 4,
                 B + (size_t)(t * V2_BK + r) * N + bn + c4);
        }
        CP_COMMIT();
    };

    issue(0, 0);
    issue(1, 1);

    for (int t = 0; t < nt; t++) {
        if (t + 2 < nt) issue(t + 2, (t + 2) % 3);
        CP_WAIT2();
        __syncthreads();

        const float* As = smem + (t % 3) * STG_WORDS;
        const float* Bs = As + V2_BM * APITCH;

#pragma unroll
        for (int kk = 0; kk < 4; kk++) {
            const int k0 = kk * 8;
            uint32_t a[4][4], b[8][2];
#pragma unroll
            for (int mi = 0; mi < 4; mi++) {
                int m = warpM * 64 + mi * 16 + g;
                a[mi][0] = __float_as_uint(As[m * APITCH + k0 + c]);
                a[mi][1] = __float_as_uint(As[(m + 8) * APITCH + k0 + c]);
                a[mi][2] = __float_as_uint(As[m * APITCH + k0 + c + 4]);
                a[mi][3] = __float_as_uint(As[(m + 8) * APITCH + k0 + c + 4]);
            }
#pragma unroll
            for (int j = 0; j < 8; j++) {
                int n = warpN * 64 + j * 8 + g;
                b[j][0] = __float_as_uint(Bs[(k0 + c) * BPITCH + n]);
                b[j][1] = __float_as_uint(Bs[(k0 + c + 4) * BPITCH + n]);
            }
#pragma unroll
            for (int mi = 0; mi < 4; mi++)
#pragma unroll
                for (int j = 0; j < 8; j++)
                    mma_tf32(acc[mi][j], a[mi][0], a[mi][1], a[mi][2], a[mi][3],
                             b[j][0], b[j][1]);
        }
        __syncthreads();
    }

#pragma unroll
    for (int mi = 0; mi < 4; mi++) {
        int row = bm + warpM * 64 + mi * 16 + g;
#pragma unroll
        for (int j = 0; j < 8; j++) {
            int col = bn + warpN * 64 + j * 8 + 2 * c;
            float2 v0, v1;
            v0.x = acc[mi][j][0]; v0.y = acc[mi][j][1];
            v1.x = acc[mi][j][2]; v1.y = acc[mi][j][3];
            *(float2*)(C + (size_t)row * N + col)       = v0;
            *(float2*)(C + (size_t)(row + 8) * N + col) = v1;
        }
    }
}

// ---------------- RoPE (in place) ----------------------------------------
__global__ __launch_bounds__(256)
void rope_kernel(float2* __restrict__ x, const float* __restrict__ cs,
                 const float* __restrict__ sn, int heads)
{
    const int idx = blockIdx.x * blockDim.x + threadIdx.x;
    const int pair = idx & 63;
    const int row  = idx >> 6;
    const int s    = (row / heads) & (SEQ - 1);
    const float c  = cs[s * 64 + pair];
    const float si = sn[s * 64 + pair];
    float2 v = x[idx];
    float2 o;
    o.x = v.x * c - v.y * si;
    o.y = v.x * si + v.y * c;
    x[idx] = o;
}

// ============ bf16-split tensor-core flash attention =====================
#define QPITCH 136
#define KPITCH 136
#define VPITCH 68
#define OFF_QH 0
#define OFF_QL (OFF_QH + 128 * QPITCH * 2)
#define OFF_KH (OFF_QL + 128 * QPITCH * 2)
#define OFF_KL (OFF_KH + 64 * KPITCH * 2)
#define OFF_VH (OFF_KL + 64 * KPITCH * 2)
#define OFF_VL (OFF_VH + 128 * VPITCH * 2)
#define ATT_SMEM (OFF_VL + 128 * VPITCH * 2)     // 139264

__device__ __forceinline__ void mma_bf16(float* d, uint32_t a0, uint32_t a1,
                                         uint32_t a2, uint32_t a3,
                                         uint32_t b0, uint32_t b1) {
    asm volatile(
        "mma.sync.aligned.m16n8k16.row.col.f32.bf16.bf16.f32 "
        "{%0,%1,%2,%3},{%4,%5,%6,%7},{%8,%9},{%0,%1,%2,%3};"
        : "+f"(d[0]), "+f"(d[1]), "+f"(d[2]), "+f"(d[3])
        : "r"(a0), "r"(a1), "r"(a2), "r"(a3), "r"(b0), "r"(b1));
}

__device__ __forceinline__ uint32_t packbf(__nv_bfloat16 lo, __nv_bfloat16 hi) {
    __nv_bfloat162 p(lo, hi);
    return *(uint32_t*)&p;
}
__device__ __forceinline__ uint32_t pack_f2(float lo, float hi) {
    return packbf(__float2bfloat16_rn(lo), __float2bfloat16_rn(hi));
}
__device__ __forceinline__ void split2(float v, __nv_bfloat16& h, __nv_bfloat16& l) {
    h = __float2bfloat16_rn(v);
    l = __float2bfloat16_rn(v - __bfloat162float(h));
}
__device__ __forceinline__ uint32_t ld32s(const __nv_bfloat16* p) {
    return *(const uint32_t*)p;
}

__global__ __launch_bounds__(256, 1)
void attention_mma(const float* __restrict__ q, const float* __restrict__ k,
                   const float* __restrict__ v, float* __restrict__ o)
{
    extern __shared__ char sm[];
    __nv_bfloat16* Qh  = (__nv_bfloat16*)(sm + OFF_QH);
    __nv_bfloat16* Ql  = (__nv_bfloat16*)(sm + OFF_QL);
    __nv_bfloat16* Kh  = (__nv_bfloat16*)(sm + OFF_KH);
    __nv_bfloat16* Kl  = (__nv_bfloat16*)(sm + OFF_KL);
    __nv_bfloat16* Vth = (__nv_bfloat16*)(sm + OFF_VH);
    __nv_bfloat16* Vtl = (__nv_bfloat16*)(sm + OFF_VL);

    const int tid  = threadIdx.x;
    const int wid  = tid >> 5;
    const int lane = tid & 31;
    const int g = lane >> 2;
    const int c = lane & 3;
    const int b  = blockIdx.z;
    const int h  = blockIdx.y;
    const int kvh = h >> 2;
    const int q0 = blockIdx.x * 128;

    const float inv_sqrt = 0.08838834764831845f;

    // ---- load + split Q (scaled) ----
    {
        const float* qb = q + ((size_t)(b * SEQ + q0) * NH + h) * HD;
#pragma unroll
        for (int i = 0; i < 16; i++) {
            int lin = i * 256 + tid;
            int r = lin >> 5, d4 = (lin & 31) << 2;
            float4 qv = *(const float4*)(qb + (size_t)r * (NH * HD) + d4);
            qv.x *= inv_sqrt; qv.y *= inv_sqrt; qv.z *= inv_sqrt; qv.w *= inv_sqrt;
            __nv_bfloat16 h0, h1, h2, h3, l0, l1, l2, l3;
            split2(qv.x, h0, l0); split2(qv.y, h1, l1);
            split2(qv.z, h2, l2); split2(qv.w, h3, l3);
            uint2 hv, lv;
            hv.x = packbf(h0, h1); hv.y = packbf(h2, h3);
            lv.x = packbf(l0, l1); lv.y = packbf(l2, l3);
            *(uint2*)(Qh + r * QPITCH + d4) = hv;
            *(uint2*)(Ql + r * QPITCH + d4) = lv;
        }
    }

    float m0 = -1e30f, m1 = -1e30f, l0s = 0.f, l1s = 0.f;
    float oacc[16][4];
#pragma unroll
    for (int j = 0; j < 16; j++)
#pragma unroll
        for (int r = 0; r < 4; r++) oacc[j][r] = 0.f;

    const float* kb0 = k + ((size_t)(b * SEQ) * NKV + kvh) * HD;
    const float* vb0 = v + ((size_t)(b * SEQ) * NKV + kvh) * HD;

    for (int kt = 0; kt < SEQ / 64; kt++) {
        __syncthreads();
        // ---- load + split K ----
        {
            const float* kb = kb0 + (size_t)(kt * 64) * KVD;
#pragma unroll
            for (int i = 0; i < 8; i++) {
                int lin = i * 256 + tid;
                int r = lin >> 5, d4 = (lin & 31) << 2;
                float4 kv = *(const float4*)(kb + (size_t)r * KVD + d4);
                __nv_bfloat16 h0, h1, h2, h3, lo0, lo1, lo2, lo3;
                split2(kv.x, h0, lo0); split2(kv.y, h1, lo1);
                split2(kv.z, h2, lo2); split2(kv.w, h3, lo3);
                uint2 hv, lv;
                hv.x = packbf(h0, h1); hv.y = packbf(h2, h3);
                lv.x = packbf(lo0, lo1); lv.y = packbf(lo2, lo3);
                *(uint2*)(Kh + r * KPITCH + d4) = hv;
                *(uint2*)(Kl + r * KPITCH + d4) = lv;
            }
        }
        // ---- load + split + transpose V ----
        {
            const float* vb = vb0 + (size_t)(kt * 64) * KVD;
            const int d  = tid & 127;
            const int rg = (tid >> 7) << 2;
#pragma unroll
            for (int it = 0; it < 8; it++) {
                int r0 = rg + it * 8;
                __nv_bfloat16 vh[4], vl[4];
#pragma unroll
                for (int i = 0; i < 4; i++) {
                    float val = vb[(size_t)(r0 + i) * KVD + d];
                    split2(val, vh[i], vl[i]);
                }
                uint2 hv, lv;
                hv.x = packbf(vh[0], vh[1]); hv.y = packbf(vh[2], vh[3]);
                lv.x = packbf(vl[0], vl[1]); lv.y = packbf(vl[2], vl[3]);
                *(uint2*)(Vth + d * VPITCH + r0) = hv;
                *(uint2*)(Vtl + d * VPITCH + r0) = lv;
            }
        }
        __syncthreads();

        // ---- S = Q @ K^T (3-term) ----
        float s[8][4];
#pragma unroll
        for (int j = 0; j < 8; j++)
#pragma unroll
            for (int r = 0; r < 4; r++) s[j][r] = 0.f;

#pragma unroll
        for (int kk = 0; kk < 8; kk++) {
            const int dofs = kk * 16 + 2 * c;
            const __nv_bfloat16* qhp = Qh + (wid * 16 + g) * QPITCH + dofs;
            const __nv_bfloat16* qlp = Ql + (wid * 16 + g) * QPITCH + dofs;
            uint32_t ah0 = ld32s(qhp),     ah1 = ld32s(qhp + 8 * QPITCH);
            uint32_t ah2 = ld32s(qhp + 8), ah3 = ld32s(qhp + 8 * QPITCH + 8);
            uint32_t al0 = ld32s(qlp),     al1 = ld32s(qlp + 8 * QPITCH);
            uint32_t al2 = ld32s(qlp + 8), al3 = ld32s(qlp + 8 * QPITCH + 8);
#pragma unroll
            for (int j = 0; j < 8; j++) {
                const __nv_bfloat16* khp = Kh + (8 * j + g) * KPITCH + dofs;
                const __nv_bfloat16* klp = Kl + (8 * j + g) * KPITCH + dofs;
                uint32_t bh0 = ld32s(khp), bh1 = ld32s(khp + 8);
                uint32_t bl0 = ld32s(klp), bl1 = ld32s(klp + 8);
                mma_bf16(s[j], ah0, ah1, ah2, ah3, bh0, bh1);
                mma_bf16(s[j], ah0, ah1, ah2, ah3, bl0, bl1);
                mma_bf16(s[j], al0, al1, al2, al3, bh0, bh1);
            }
        }

        // ---- online softmax ----
        float mx0 = s[0][0], mx1 = s[0][2];
#pragma unroll
        for (int j = 0; j < 8; j++) {
            mx0 = fmaxf(mx0, fmaxf(s[j][0], s[j][1]));
            mx1 = fmaxf(mx1, fmaxf(s[j][2], s[j][3]));
        }
        mx0 = fmaxf(mx0, __shfl_xor_sync(0xffffffffu, mx0, 1));
        mx0 = fmaxf(mx0, __shfl_xor_sync(0xffffffffu, mx0, 2));
        mx1 = fmaxf(mx1, __shfl_xor_sync(0xffffffffu, mx1, 1));
        mx1 = fmaxf(mx1, __shfl_xor_sync(0xffffffffu, mx1, 2));
        float mn0 = fmaxf(m0, mx0), mn1 = fmaxf(m1, mx1);
        float f0 = __expf(m0 - mn0), f1 = __expf(m1 - mn1);
        float rs0 = 0.f, rs1 = 0.f;
#pragma unroll
        for (int j = 0; j < 8; j++) {
            s[j][0] = __expf(s[j][0] - mn0);
            s[j][1] = __expf(s[j][1] - mn0);
            s[j][2] = __expf(s[j][2] - mn1);
            s[j][3] = __expf(s[j][3] - mn1);
            rs0 += s[j][0] + s[j][1];
            rs1 += s[j][2] + s[j][3];
        }
        rs0 += __shfl_xor_sync(0xffffffffu, rs0, 1);
        rs0 += __shfl_xor_sync(0xffffffffu, rs0, 2);
        rs1 += __shfl_xor_sync(0xffffffffu, rs1, 1);
        rs1 += __shfl_xor_sync(0xffffffffu, rs1, 2);
        l0s = l0s * f0 + rs0;
        l1s = l1s * f1 + rs1;
        m0 = mn0; m1 = mn1;
#pragma unroll
        for (int j = 0; j < 16; j++) {
            oacc[j][0] *= f0; oacc[j][1] *= f0;
            oacc[j][2] *= f1; oacc[j][3] *= f1;
        }

        // ---- O += P @ V (3-term), P from S frags in-register ----
#pragma unroll
        for (int kk = 0; kk < 4; kk++) {
            const int j0 = 2 * kk, j1 = 2 * kk + 1;
            uint32_t ph0 = pack_f2(s[j0][0], s[j0][1]);
            uint32_t ph1 = pack_f2(s[j0][2], s[j0][3]);
            uint32_t ph2 = pack_f2(s[j1][0], s[j1][1]);
            uint32_t ph3 = pack_f2(s[j1][2], s[j1][3]);
            __nv_bfloat162 h0 = *(__nv_bfloat162*)&ph0;
            __nv_bfloat162 h1 = *(__nv_bfloat162*)&ph1;
            __nv_bfloat162 h2 = *(__nv_bfloat162*)&ph2;
            __nv_bfloat162 h3 = *(__nv_bfloat162*)&ph3;
            uint32_t pl0 = pack_f2(s[j0][0] - __bfloat162float(h0.x),
                                   s[j0][1] - __bfloat162float(h0.y));
            uint32_t pl1 = pack_f2(s[j0][2] - __bfloat162float(h1.x),
                                   s[j0][3] - __bfloat162float(h1.y));
            uint32_t pl2 = pack_f2(s[j1][0] - __bfloat162float(h2.x),
                                   s[j1][1] - __bfloat162float(h2.y));
            uint32_t pl3 = pack_f2(s[j1][2] - __bfloat162float(h3.x),
                                   s[j1][3] - __bfloat162float(h3.y));
            const int kofs = kk * 16 + 2 * c;
#pragma unroll
            for (int j = 0; j < 16; j++) {
                const __nv_bfloat16* vhp = Vth + (8 * j + g) * VPITCH + kofs;
                const __nv_bfloat16* vlp = Vtl + (8 * j + g) * VPITCH + kofs;
                uint32_t bh0 = ld32s(vhp), bh1 = ld32s(vhp + 8);
                uint32_t bl0 = ld32s(vlp), bl1 = ld32s(vlp + 8);
                mma_bf16(oacc[j], ph0, ph1, ph2, ph3, bh0, bh1);
                mma_bf16(oacc[j], ph0, ph1, ph2, ph3, bl0, bl1);
                mma_bf16(oacc[j], pl0, pl1, pl2, pl3, bh0, bh1);
            }
        }
    }

    // ---- normalize + write (tf32-rounded for the following GEMM) ----
    const float inv0 = 1.f / l0s, inv1 = 1.f / l1s;
    float* ob  = o + ((size_t)(b * SEQ + q0 + wid * 16 + g) * NH + h) * HD;
    float* ob8 = ob + (size_t)8 * NH * HD;
#pragma unroll
    for (int j = 0; j < 16; j++) {
        int col = j * 8 + 2 * c;
        float2 v0, v1;
        v0.x = f2tf_f(oacc[j][0] * inv0); v0.y = f2tf_f(oacc[j][1] * inv0);
        v1.x = f2tf_f(oacc[j][2] * inv1); v1.y = f2tf_f(oacc[j][3] * inv1);
        *(float2*)(ob + col)  = v0;
        *(float2*)(ob8 + col) = v1;
    }
}

// ---------------- launch -------------------------------------------------
extern "C" void kernel_launch(void* const* d_in, const int* in_sizes, int n_in,
                              void* d_out, int out_size)
{
    (void)in_sizes; (void)n_in; (void)out_size;
    const float* x  = (const float*)d_in[0];
    const float* wq = (const float*)d_in[1];
    const float* wk = (const float*)d_in[2];
    const float* wv = (const float*)d_in[3];
    const float* wo = (const float*)d_in[4];
    const float* fc = (const float*)d_in[5];
    const float* fs = (const float*)d_in[6];
    float* out = (float*)d_out;

    float *xq, *xk, *xv, *attn, *xr, *wqr, *wkr, *wvr, *wor;
    cudaGetSymbolAddress((void**)&xq,   g_xq);
    cudaGetSymbolAddress((void**)&xk,   g_xk);
    cudaGetSymbolAddress((void**)&xv,   g_xv);
    cudaGetSymbolAddress((void**)&attn, g_attn);
    cudaGetSymbolAddress((void**)&xr,   g_xr);
    cudaGetSymbolAddress((void**)&wqr,  g_wqr);
    cudaGetSymbolAddress((void**)&wkr,  g_wkr);
    cudaGetSymbolAddress((void**)&wvr,  g_wvr);
    cudaGetSymbolAddress((void**)&wor,  g_wor);

    cudaFuncSetAttribute(tf32_gemm2,
                         cudaFuncAttributeMaxDynamicSharedMemorySize, V2_SMEM);
    cudaFuncSetAttribute(attention_mma,
                         cudaFuncAttributeMaxDynamicSharedMemorySize, ATT_SMEM);

    // tf32 pre-rounding
    round_kernel<<<(MTOT * DIM / 4) / 256, 256>>>((const float4*)x, (float4*)xr);
    round_kernel<<<((size_t)DIM * DIM / 4) / 256, 256>>>((const float4*)wq, (float4*)wqr);
    round_kernel<<<((size_t)DIM * KVD / 4) / 256, 256>>>((const float4*)wk, (float4*)wkr);
    round_kernel<<<((size_t)DIM * KVD / 4) / 256, 256>>>((const float4*)wv, (float4*)wvr);
    round_kernel<<<((size_t)DIM * DIM / 4) / 256, 256>>>((const float4*)wo, (float4*)wor);

    // QKV projections
    tf32_gemm2<<<dim3(DIM / V2_BN, MTOT / V2_BM), 256, V2_SMEM>>>(xr, wqr, xq, MTOT, DIM, DIM);
    tf32_gemm2<<<dim3(KVD / V2_BN, MTOT / V2_BM), 256, V2_SMEM>>>(xr, wkr, xk, MTOT, KVD, DIM);
    tf32_gemm2<<<dim3(KVD / V2_BN, MTOT / V2_BM), 256, V2_SMEM>>>(xr, wvr, xv, MTOT, KVD, DIM);

    // RoPE
    rope_kernel<<<(MTOT * NH * (HD / 2)) / 256, 256>>>((float2*)xq, fc, fs, NH);
    rope_kernel<<<(MTOT * NKV * (HD / 2)) / 256, 256>>>((float2*)xk, fc, fs, NKV);

    // attention (bf16-split mma)
    attention_mma<<<dim3(SEQ / 128, NH, BATCH), 256, ATT_SMEM>>>(xq, xk, xv, attn);

    // output projection
    tf32_gemm2<<<dim3(DIM / V2_BN, MTOT / V2_BM), 256, V2_SMEM>>>(attn, wor, out, MTOT, DIM, DIM);
}